// round 5
// baseline (speedup 1.0000x reference)
#include <cuda_runtime.h>
#include <math.h>

#define BB 16
#define LL 16384
#define CC 256
#define NHH 8
#define TM 128
#define CHUNKS (LL/TM)   // 128
#define BK 16
#define BN 128
#define NT 256
#define ATT_SCALE 0.17677669529663687f  // 1/sqrt(32)

// ---- scratch (no allocations allowed) ----
__device__ float g_wt[BB*NHH*CC];                       // q-folded key projector
__device__ float g_cb[BB*NHH];                          // q . b_kv bias term
__device__ float g_pmax[BB*NHH*CHUNKS];
__device__ float g_psum[BB*NHH*CHUNKS];
__device__ float g_pacc[(size_t)BB*NHH*CHUNKS*CC];      // 16.8 MB partial weighted m
__device__ float g_wm[BB*NHH*CC];                       // softmax-weighted m per head

__device__ __forceinline__ float blk_sum(float v, float* red) {
    int tid = threadIdx.x, lane = tid & 31, w = tid >> 5;
    #pragma unroll
    for (int o = 16; o; o >>= 1) v += __shfl_xor_sync(0xffffffffu, v, o);
    if (lane == 0) red[w] = v;
    __syncthreads();
    if (w == 0) {
        float r = (lane < 8) ? red[lane] : 0.f;
        #pragma unroll
        for (int o = 4; o; o >>= 1) r += __shfl_xor_sync(0xffffffffu, r, o);
        if (lane == 0) red[0] = r;
    }
    __syncthreads();
    float out = red[0];
    __syncthreads();
    return out;
}

// ============================================================
// Kernel 1: per-batch prep. qn = LN(query); qp = qn@W_q + b_q;
// w_tilde[b,h,c] = sum_d qp[h*32+d] * W_kv[c, h*32+d]; cb[b,h] = qp_h . b_kv_h
// ============================================================
__global__ void prep_kernel(const float* __restrict__ query,
                            const float* __restrict__ W_q,  const float* __restrict__ b_q,
                            const float* __restrict__ W_kv, const float* __restrict__ b_kv,
                            const float* __restrict__ g_q,  const float* __restrict__ be_q) {
    __shared__ float q0[CC], qn[CC], qp[CC], red[32];
    int b = blockIdx.x, tid = threadIdx.x;
    float x = query[b*CC + tid];
    q0[tid] = x;
    __syncthreads();
    float s  = blk_sum(x, red);
    float s2 = blk_sum(x*x, red);
    float mean = s * (1.f/CC);
    float rstd = rsqrtf(s2*(1.f/CC) - mean*mean + 1e-5f);
    qn[tid] = (x - mean) * rstd * g_q[tid] + be_q[tid];
    __syncthreads();
    float acc = b_q[tid];
    #pragma unroll 8
    for (int c = 0; c < CC; c++) acc = fmaf(qn[c], W_q[c*CC + tid], acc);
    qp[tid] = acc;
    __syncthreads();
    int c = tid;
    #pragma unroll
    for (int h = 0; h < NHH; h++) {
        float sw = 0.f;
        #pragma unroll
        for (int d = 0; d < 32; d++) sw = fmaf(qp[h*32+d], W_kv[c*(2*CC) + h*32 + d], sw);
        g_wt[(b*NHH + h)*CC + c] = sw;
    }
    if (tid < NHH) {
        float sb = 0.f;
        for (int d = 0; d < 32; d++) sb = fmaf(qp[tid*32+d], b_kv[tid*32+d], sb);
        g_cb[b*NHH + tid] = sb;
    }
}

// ============================================================
// Kernel 2 (heavy): per (b, 128-row chunk):
//   m = LN(relu(X@W_ip + b_ip)) kept in SMEM,
//   scores via m . w_tilde * scale * ior, chunk-local softmax,
//   partial acc[h][c] = sum_l p[l][h]*m[l][c] -> global partials.
// ============================================================
__global__ __launch_bounds__(NT, 1)
void main_kernel(const float* __restrict__ mem,  const float* __restrict__ W_ip,
                 const float* __restrict__ b_ip, const float* __restrict__ g_ip,
                 const float* __restrict__ be_ip,const float* __restrict__ ior) {
    extern __shared__ float sm[];
    float* Cs  = sm;                       // TM*(CC+1) = 32896
    float* Xs  = Cs  + TM*(CC+1);          // TM*BK   = 2048
    float* Ws  = Xs  + TM*BK;              // BK*BN   = 2048
    float* wts = Ws  + BK*BN;              // NHH*CC  = 2048
    float* Ss  = wts + NHH*CC;             // TM*NHH  = 1024
    float* Pm  = Ss  + TM*NHH;             // TM*NHH  = 1024
    float* gS  = Pm  + TM*NHH;             // CC
    float* bS  = gS  + CC;                 // CC
    float* cbS = bS  + CC;                 // NHH

    int tid = threadIdx.x;
    int chunk = blockIdx.x, b = blockIdx.y;
    int l0 = chunk * TM;
    const float* Xg = mem + ((size_t)b*LL + l0)*CC;

    for (int i = tid; i < NHH*CC; i += NT) wts[i] = g_wt[b*NHH*CC + i];
    gS[tid] = g_ip[tid];
    bS[tid] = be_ip[tid];
    if (tid < NHH) cbS[tid] = g_cb[b*NHH + tid];

    int ty = tid >> 4, tx = tid & 15;
    int xr0 = tid >> 2, xk = (tid & 3) * 4;
    int wk0 = tid >> 5, wj0 = (tid & 31) * 4;

    // ---- GEMM: two 128-col n-blocks, prefetched k-chunks ----
    for (int nb = 0; nb < 2; nb++) {
        float acc[8][8];
        #pragma unroll
        for (int i = 0; i < 8; i++)
            #pragma unroll
            for (int j = 0; j < 8; j++) acc[i][j] = 0.f;

        const float* Wg = W_ip + nb*BN;
        float4 xv0 = *(const float4*)(Xg + xr0*CC + xk);
        float4 xv1 = *(const float4*)(Xg + (xr0+64)*CC + xk);
        float4 wv0 = *(const float4*)(Wg + wk0*CC + wj0);
        float4 wv1 = *(const float4*)(Wg + (wk0+8)*CC + wj0);

        for (int k0 = 0; k0 < CC; k0 += BK) {
            __syncthreads();
            *(float4*)&Xs[xr0*BK + xk]      = xv0;
            *(float4*)&Xs[(xr0+64)*BK + xk] = xv1;
            *(float4*)&Ws[wk0*BN + wj0]     = wv0;
            *(float4*)&Ws[(wk0+8)*BN + wj0] = wv1;
            __syncthreads();
            if (k0 + BK < CC) {
                xv0 = *(const float4*)(Xg + xr0*CC + (k0+BK) + xk);
                xv1 = *(const float4*)(Xg + (xr0+64)*CC + (k0+BK) + xk);
                wv0 = *(const float4*)(Wg + (k0+BK+wk0)*CC + wj0);
                wv1 = *(const float4*)(Wg + (k0+BK+wk0+8)*CC + wj0);
            }
            #pragma unroll
            for (int kk = 0; kk < BK; kk++) {
                float a[8];
                #pragma unroll
                for (int i = 0; i < 8; i++) a[i] = Xs[(ty*8+i)*BK + kk];
                float4 b0 = *(float4*)&Ws[kk*BN + tx*8];
                float4 b1 = *(float4*)&Ws[kk*BN + tx*8 + 4];
                float bb[8] = {b0.x,b0.y,b0.z,b0.w,b1.x,b1.y,b1.z,b1.w};
                #pragma unroll
                for (int i = 0; i < 8; i++)
                    #pragma unroll
                    for (int j = 0; j < 8; j++)
                        acc[i][j] = fmaf(a[i], bb[j], acc[i][j]);
            }
        }
        // epilogue: +bias, relu -> Cs (vectorized, padded rows)
        #pragma unroll
        for (int i = 0; i < 8; i++) {
            int row = ty*8 + i;
            int col = nb*BN + tx*8;
            float4 o0, o1;
            o0.x = fmaxf(acc[i][0] + b_ip[col+0], 0.f);
            o0.y = fmaxf(acc[i][1] + b_ip[col+1], 0.f);
            o0.z = fmaxf(acc[i][2] + b_ip[col+2], 0.f);
            o0.w = fmaxf(acc[i][3] + b_ip[col+3], 0.f);
            o1.x = fmaxf(acc[i][4] + b_ip[col+4], 0.f);
            o1.y = fmaxf(acc[i][5] + b_ip[col+5], 0.f);
            o1.z = fmaxf(acc[i][6] + b_ip[col+6], 0.f);
            o1.w = fmaxf(acc[i][7] + b_ip[col+7], 0.f);
            // row stride CC+1 (odd) -> column accesses later are conflict-free;
            // scalar stores since 257 breaks 16B alignment
            float* dst = &Cs[row*(CC+1) + col];
            dst[0]=o0.x; dst[1]=o0.y; dst[2]=o0.z; dst[3]=o0.w;
            dst[4]=o1.x; dst[5]=o1.y; dst[6]=o1.z; dst[7]=o1.w;
        }
    }
    __syncthreads();

    // ---- LN per row + fused scores (warp per row) ----
    int w = tid >> 5, lane = tid & 31;
    for (int r = w; r < TM; r += 8) {
        float vals[8]; float s = 0.f, s2 = 0.f;
        #pragma unroll
        for (int i = 0; i < 8; i++) {
            float x = Cs[r*(CC+1) + lane + 32*i];
            vals[i] = x; s += x; s2 += x*x;
        }
        #pragma unroll
        for (int o = 16; o; o >>= 1) {
            s  += __shfl_xor_sync(0xffffffffu, s,  o);
            s2 += __shfl_xor_sync(0xffffffffu, s2, o);
        }
        float mean = s * (1.f/CC);
        float rstd = rsqrtf(s2*(1.f/CC) - mean*mean + 1e-5f);
        float ph[8];
        #pragma unroll
        for (int h = 0; h < 8; h++) ph[h] = 0.f;
        #pragma unroll
        for (int i = 0; i < 8; i++) {
            int c = lane + 32*i;
            float m = (vals[i] - mean) * rstd * gS[c] + bS[c];
            Cs[r*(CC+1) + c] = m;
            #pragma unroll
            for (int h = 0; h < 8; h++) ph[h] = fmaf(m, wts[h*CC + c], ph[h]);
        }
        #pragma unroll
        for (int h = 0; h < 8; h++)
            #pragma unroll
            for (int o = 16; o; o >>= 1) ph[h] += __shfl_xor_sync(0xffffffffu, ph[h], o);
        if (lane == 0) {
            #pragma unroll
            for (int h = 0; h < 8; h++) {
                float sc = (ph[h] + cbS[h]) * ATT_SCALE
                         * ior[((size_t)(b*NHH + h))*LL + l0 + r];
                Ss[r*NHH + h] = sc;
            }
        }
    }
    __syncthreads();

    // ---- chunk-local softmax: warp h handles head h over 128 rows ----
    {
        float sv[4]; float mx = -1e30f;
        #pragma unroll
        for (int t = 0; t < 4; t++) {
            float sc = Ss[(lane + 32*t)*NHH + w];
            sv[t] = sc; mx = fmaxf(mx, sc);
        }
        #pragma unroll
        for (int o = 16; o; o >>= 1) mx = fmaxf(mx, __shfl_xor_sync(0xffffffffu, mx, o));
        float sum = 0.f;
        #pragma unroll
        for (int t = 0; t < 4; t++) {
            float p = __expf(sv[t] - mx);
            Pm[(lane + 32*t)*NHH + w] = p;
            sum += p;
        }
        #pragma unroll
        for (int o = 16; o; o >>= 1) sum += __shfl_xor_sync(0xffffffffu, sum, o);
        if (lane == 0) {
            g_pmax[(b*NHH + w)*CHUNKS + chunk] = mx;
            g_psum[(b*NHH + w)*CHUNKS + chunk] = sum;
        }
    }
    __syncthreads();

    // ---- partial weighted-m accumulation: thread t owns channel c=t ----
    float a8[8];
    #pragma unroll
    for (int h = 0; h < 8; h++) a8[h] = 0.f;
    int c = tid;
    #pragma unroll 2
    for (int r = 0; r < TM; r++) {
        float m = Cs[r*(CC+1) + c];
        float4 p0 = *(float4*)&Pm[r*NHH];
        float4 p1 = *(float4*)&Pm[r*NHH + 4];
        a8[0] = fmaf(p0.x, m, a8[0]);
        a8[1] = fmaf(p0.y, m, a8[1]);
        a8[2] = fmaf(p0.z, m, a8[2]);
        a8[3] = fmaf(p0.w, m, a8[3]);
        a8[4] = fmaf(p1.x, m, a8[4]);
        a8[5] = fmaf(p1.y, m, a8[5]);
        a8[6] = fmaf(p1.z, m, a8[6]);
        a8[7] = fmaf(p1.w, m, a8[7]);
    }
    #pragma unroll
    for (int h = 0; h < 8; h++)
        g_pacc[((size_t)(b*NHH + h)*CHUNKS + chunk)*CC + c] = a8[h];
}

// ============================================================
// Kernel 3: combine chunk partials per (b,h) -> normalized weighted m
// ============================================================
__global__ void reduce_kernel() {
    __shared__ float wfac[CHUNKS];
    __shared__ float red[32];
    __shared__ float s_gmax;
    int bh = blockIdx.x, tid = threadIdx.x;
    int lane = tid & 31, w = tid >> 5;

    float v = (tid < CHUNKS) ? g_pmax[bh*CHUNKS + tid] : -1e30f;
    float m = v;
    #pragma unroll
    for (int o = 16; o; o >>= 1) m = fmaxf(m, __shfl_xor_sync(0xffffffffu, m, o));
    if (lane == 0) red[w] = m;
    __syncthreads();
    if (w == 0) {
        float r = (lane < 8) ? red[lane] : -1e30f;
        #pragma unroll
        for (int o = 4; o; o >>= 1) r = fmaxf(r, __shfl_xor_sync(0xffffffffu, r, o));
        if (lane == 0) s_gmax = r;
    }
    __syncthreads();
    float gmax = s_gmax;

    float contrib = 0.f;
    if (tid < CHUNKS) {
        float wf = __expf(v - gmax);
        wfac[tid] = wf;
        contrib = wf * g_psum[bh*CHUNKS + tid];
    }
    float tot = blk_sum(contrib, red);
    float inv = 1.f / tot;

    int c = tid;
    float acc = 0.f;
    const float* pa = g_pacc + (size_t)bh*CHUNKS*CC;
    #pragma unroll 4
    for (int i = 0; i < CHUNKS; i++) acc = fmaf(pa[(size_t)i*CC + c], wfac[i], acc);
    g_wm[bh*CC + c] = acc * inv;
}

// ============================================================
// Kernel 4: out = wm @ Wv + b_v; x = out + query; LN; FFN(gelu); y = x + ffn
// ============================================================
__global__ void final_kernel(const float* __restrict__ query,
                             const float* __restrict__ W_kv, const float* __restrict__ b_kv,
                             const float* __restrict__ g_f,  const float* __restrict__ be_f,
                             const float* __restrict__ W1,   const float* __restrict__ b1,
                             const float* __restrict__ W2,   const float* __restrict__ b2,
                             float* __restrict__ out) {
    __shared__ float wm[NHH*CC], xs[CC], hb[CC], tf[2*CC], red[32];
    int b = blockIdx.x, tid = threadIdx.x;
    for (int i = tid; i < NHH*CC; i += NT) wm[i] = g_wm[b*NHH*CC + i];
    __syncthreads();

    int j = tid, h = j >> 5;
    float o = b_kv[CC + j];
    const float* wmh = wm + h*CC;
    #pragma unroll 8
    for (int c = 0; c < CC; c++) o = fmaf(wmh[c], W_kv[c*(2*CC) + CC + j], o);
    float x = o + query[b*CC + j];
    xs[j] = x;
    __syncthreads();

    float s  = blk_sum(x, red);
    float s2 = blk_sum(x*x, red);
    float mean = s * (1.f/CC);
    float rstd = rsqrtf(s2*(1.f/CC) - mean*mean + 1e-5f);
    hb[j] = (x - mean) * rstd * g_f[j] + be_f[j];
    __syncthreads();

    #pragma unroll
    for (int t = 0; t < 2; t++) {
        int f = tid + t*NT;
        float a = b1[f];
        #pragma unroll 8
        for (int c = 0; c < CC; c++) a = fmaf(hb[c], W1[c*(2*CC) + f], a);
        tf[f] = 0.5f * a * (1.f + erff(a * 0.7071067811865475f));  // exact gelu
    }
    __syncthreads();

    float y = b2[j];
    #pragma unroll 8
    for (int f = 0; f < 2*CC; f++) y = fmaf(tf[f], W2[f*CC + j], y);
    out[b*CC + j] = xs[j] + y;
}

// ============================================================
extern "C" void kernel_launch(void* const* d_in, const int* in_sizes, int n_in,
                              void* d_out, int out_size) {
    const float* query = (const float*)d_in[0];
    const float* mem   = (const float*)d_in[1];
    const float* ior   = (const float*)d_in[2];
    const float* W_ip  = (const float*)d_in[3];
    const float* b_ip  = (const float*)d_in[4];
    const float* g_ip  = (const float*)d_in[5];
    const float* be_ip = (const float*)d_in[6];
    const float* W_q   = (const float*)d_in[7];
    const float* b_q   = (const float*)d_in[8];
    const float* W_kv  = (const float*)d_in[9];
    const float* b_kv  = (const float*)d_in[10];
    const float* g_q   = (const float*)d_in[11];
    const float* be_q  = (const float*)d_in[12];
    const float* g_f   = (const float*)d_in[13];
    const float* be_f  = (const float*)d_in[14];
    const float* W1    = (const float*)d_in[15];
    const float* b1    = (const float*)d_in[16];
    const float* W2    = (const float*)d_in[17];
    const float* b2    = (const float*)d_in[18];
    float* out = (float*)d_out;

    prep_kernel<<<BB, NT>>>(query, W_q, b_q, W_kv, b_kv, g_q, be_q);

    size_t smem = (size_t)(TM*(CC+1) + TM*BK + BK*BN + NHH*CC + 2*TM*NHH + 2*CC + NHH)
                * sizeof(float);  // 166432 B
    cudaFuncSetAttribute(main_kernel, cudaFuncAttributeMaxDynamicSharedMemorySize,
                         (int)smem);
    main_kernel<<<dim3(CHUNKS, BB), NT, smem>>>(mem, W_ip, b_ip, g_ip, be_ip, ior);

    reduce_kernel<<<BB*NHH, NT>>>();
    final_kernel<<<BB, NT>>>(query, W_kv, b_kv, g_f, be_f, W1, b1, W2, b2, out);
}

// round 17
// speedup vs baseline: 1.7142x; 1.7142x over previous
#include <cuda_runtime.h>
#include <math.h>
#include <stdint.h>

#define BB 16
#define LL 16384
#define CC 256
#define NHH 8
#define TM 128
#define CHUNKS (LL/TM)   // 128
#define NT 256
#define BKP 36           // padded k-stride (floats) for staging tiles
#define ATT_SCALE 0.17677669529663687f  // 1/sqrt(32)

// SMEM float-offset layout (GEMM A/B staging aliases under Cs):
//   A tile: floats [0, 4608)      = 128 rows x 36
//   B tile: floats [4608, 13824)  = 256 rows x 36
#define CS_F   0                     // 128*257 = 32896 floats
#define WTS_F  32896                 // 2048
#define SS_F   (WTS_F+2048)          // 1024
#define PM_F   (SS_F+1024)           // 1024
#define GS_F   (PM_F+1024)           // 256
#define BS_F   (GS_F+256)            // 256
#define BIP_F  (BS_F+256)            // 256
#define CBS_F  (BIP_F+256)           // 16
#define SMEM_FLOATS (CBS_F+16)
#define SMEM_BYTES  (SMEM_FLOATS*4)  // 151104 B

// ---- scratch (no allocations allowed) ----
__device__ float g_wt[BB*NHH*CC];
__device__ float g_cb[BB*NHH];
__device__ float g_pmax[BB*NHH*CHUNKS];
__device__ float g_psum[BB*NHH*CHUNKS];
__device__ float g_pacc[(size_t)BB*NHH*CHUNKS*CC];
__device__ float g_wm[BB*NHH*CC];
__device__ float g_wipT[CC*CC];      // W_ip transposed: [n][k], k-contiguous

// ================= helpers =================
__device__ __forceinline__ uint32_t smem_u32(const void* p) {
    uint32_t a;
    asm("{ .reg .u64 t; cvta.to.shared.u64 t, %1; cvt.u32.u64 %0, t; }"
        : "=r"(a) : "l"(p));
    return a;
}
__device__ __forceinline__ float to_tf32(float x) {
    float y;
    asm("cvt.rna.tf32.f32 %0, %1;" : "=f"(y) : "f"(x));
    return y;
}
__device__ __forceinline__ void ldsm4(uint32_t& r0, uint32_t& r1,
                                      uint32_t& r2, uint32_t& r3, uint32_t a) {
    asm volatile("ldmatrix.sync.aligned.m8n8.x4.shared.b16 {%0,%1,%2,%3}, [%4];"
                 : "=r"(r0), "=r"(r1), "=r"(r2), "=r"(r3) : "r"(a));
}
__device__ __forceinline__ void mma_tf32(float* d, const uint32_t* a,
                                         uint32_t b0, uint32_t b1) {
    asm volatile(
        "mma.sync.aligned.m16n8k8.row.col.f32.tf32.tf32.f32 "
        "{%0,%1,%2,%3}, {%4,%5,%6,%7}, {%8,%9}, {%0,%1,%2,%3};"
        : "+f"(d[0]), "+f"(d[1]), "+f"(d[2]), "+f"(d[3])
        : "r"(a[0]), "r"(a[1]), "r"(a[2]), "r"(a[3]), "r"(b0), "r"(b1));
}

// block reduction valid for blockDim 256 or 512
__device__ __forceinline__ float blk_sum(float v, float* red) {
    int tid = threadIdx.x, lane = tid & 31, w = tid >> 5;
    int nw = blockDim.x >> 5;
    #pragma unroll
    for (int o = 16; o; o >>= 1) v += __shfl_xor_sync(0xffffffffu, v, o);
    if (lane == 0) red[w] = v;
    __syncthreads();
    if (w == 0) {
        float r = (lane < nw) ? red[lane] : 0.f;
        #pragma unroll
        for (int o = 16; o; o >>= 1) r += __shfl_xor_sync(0xffffffffu, r, o);
        if (lane == 0) red[0] = r;
    }
    __syncthreads();
    float out = red[0];
    __syncthreads();
    return out;
}

// ============================================================
// Kernel 0: transpose W_ip -> g_wipT  (n-major, k-contiguous)
// ============================================================
__global__ void transpose_wip(const float* __restrict__ W) {
    __shared__ float t[32][33];
    int bx = blockIdx.x * 32, by = blockIdx.y * 32;
    t[threadIdx.y][threadIdx.x] = W[(by + threadIdx.y) * CC + bx + threadIdx.x];
    __syncthreads();
    g_wipT[(bx + threadIdx.y) * CC + by + threadIdx.x] = t[threadIdx.x][threadIdx.y];
}

// ============================================================
// Kernel 1: per-batch prep (unchanged, 256 threads)
// ============================================================
__global__ void prep_kernel(const float* __restrict__ query,
                            const float* __restrict__ W_q,  const float* __restrict__ b_q,
                            const float* __restrict__ W_kv, const float* __restrict__ b_kv,
                            const float* __restrict__ g_q,  const float* __restrict__ be_q) {
    __shared__ float q0[CC], qn[CC], qp[CC], red[32];
    int b = blockIdx.x, tid = threadIdx.x;
    float x = query[b*CC + tid];
    q0[tid] = x;
    __syncthreads();
    float s  = blk_sum(x, red);
    float s2 = blk_sum(x*x, red);
    float mean = s * (1.f/CC);
    float rstd = rsqrtf(s2*(1.f/CC) - mean*mean + 1e-5f);
    qn[tid] = (x - mean) * rstd * g_q[tid] + be_q[tid];
    __syncthreads();
    float acc = b_q[tid];
    #pragma unroll 8
    for (int c = 0; c < CC; c++) acc = fmaf(qn[c], W_q[c*CC + tid], acc);
    qp[tid] = acc;
    __syncthreads();
    int c = tid;
    #pragma unroll
    for (int h = 0; h < NHH; h++) {
        float sw = 0.f;
        #pragma unroll
        for (int d = 0; d < 32; d++) sw = fmaf(qp[h*32+d], W_kv[c*(2*CC) + h*32 + d], sw);
        g_wt[(b*NHH + h)*CC + c] = sw;
    }
    if (tid < NHH) {
        float sb = 0.f;
        for (int d = 0; d < 32; d++) sb = fmaf(qp[tid*32+d], b_kv[tid*32+d], sb);
        g_cb[b*NHH + tid] = sb;
    }
}

// ============================================================
// Kernel 2 (heavy): mma.sync tf32 GEMM + fused LN/scores/softmax/pacc
// ============================================================
__global__ __launch_bounds__(NT, 1)
void main_kernel(const float* __restrict__ mem,  const float* __restrict__ b_ip,
                 const float* __restrict__ g_ip, const float* __restrict__ be_ip,
                 const float* __restrict__ ior) {
    extern __shared__ float sm[];
    float* Cs   = sm + CS_F;
    float* Xs   = sm;            // A staging, aliases Cs
    float* Bs   = sm + 4608;     // B staging, aliases Cs
    float* wts  = sm + WTS_F;
    float* Ss   = sm + SS_F;
    float* Pm   = sm + PM_F;
    float* gS   = sm + GS_F;
    float* bS   = sm + BS_F;
    float* bipS = sm + BIP_F;
    float* cbS  = sm + CBS_F;

    int tid = threadIdx.x;
    int wid = tid >> 5, lane = tid & 31;
    int chunk = blockIdx.x, b = blockIdx.y;
    int l0 = chunk * TM;
    const float* Xg = mem + ((size_t)b*LL + l0)*CC;

    // param loads (non-aliased region)
    for (int i = tid; i < NHH*CC; i += NT) wts[i] = g_wt[b*NHH*CC + i];
    gS[tid]   = g_ip[tid];
    bS[tid]   = be_ip[tid];
    bipS[tid] = b_ip[tid];
    if (tid < NHH) cbS[tid] = g_cb[b*NHH + tid];

    // ---- warp tiling: wr in 0..3 (rows wr*32), wc in 0..1 (cols wc*128) ----
    int wr = wid & 3, wc = wid >> 2;
    int t = lane & 3, g = lane >> 2;

    float acc[2][16][4];
    #pragma unroll
    for (int mt = 0; mt < 2; mt++)
        #pragma unroll
        for (int nt = 0; nt < 16; nt++)
            #pragma unroll
            for (int e = 0; e < 4; e++) acc[mt][nt][e] = 0.f;

    // ldmatrix per-lane addresses (ks=0)
    int mIdx = lane >> 3, rIdx = lane & 7;
    uint32_t xs0 = smem_u32(Xs), bs0 = smem_u32(Bs);
    uint32_t aAddr[2];
    #pragma unroll
    for (int mt = 0; mt < 2; mt++) {
        int rowA = wr*32 + mt*16 + (mIdx & 1)*8 + rIdx;
        aAddr[mt] = xs0 + (uint32_t)(rowA*BKP + (mIdx >> 1)*4) * 4;
    }
    // B: matrices {rows 0-7 k0-3, rows 0-7 k4-7, rows 8-15 k0-3, rows 8-15 k4-7}
    int rowB = (mIdx >> 1)*8 + rIdx;
    uint32_t bAddr = bs0 + (uint32_t)((wc*128 + rowB)*BKP + (mIdx & 1)*4) * 4;

    // ---- GEMM: 8 K-blocks of 32 ----
    for (int kb = 0; kb < 8; kb++) {
        __syncthreads();
        // stage A: 128x32 tf32
        #pragma unroll
        for (int i = 0; i < 4; i++) {
            int f = tid + i*NT;
            int row = f >> 3, c4 = (f & 7) << 2;
            float4 v = *(const float4*)(Xg + row*CC + kb*32 + c4);
            v.x = to_tf32(v.x); v.y = to_tf32(v.y);
            v.z = to_tf32(v.z); v.w = to_tf32(v.w);
            *(float4*)&Xs[row*BKP + c4] = v;
        }
        // stage B: 256x32 tf32 (from n-major g_wipT)
        #pragma unroll
        for (int i = 0; i < 8; i++) {
            int f = tid + i*NT;
            int n = f >> 3, c4 = (f & 7) << 2;
            float4 v = *(const float4*)(g_wipT + n*CC + kb*32 + c4);
            v.x = to_tf32(v.x); v.y = to_tf32(v.y);
            v.z = to_tf32(v.z); v.w = to_tf32(v.w);
            *(float4*)&Bs[n*BKP + c4] = v;
        }
        __syncthreads();

        #pragma unroll
        for (int ks = 0; ks < 4; ks++) {
            uint32_t ko = (uint32_t)ks * 32;   // 8 floats = 32 bytes
            uint32_t af[2][4];
            #pragma unroll
            for (int mt = 0; mt < 2; mt++)
                ldsm4(af[mt][0], af[mt][1], af[mt][2], af[mt][3], aAddr[mt] + ko);
            #pragma unroll
            for (int j = 0; j < 8; j++) {
                uint32_t b0a, b1a, b0b, b1b;
                ldsm4(b0a, b1a, b0b, b1b, bAddr + (uint32_t)(j*16*BKP)*4 + ko);
                #pragma unroll
                for (int mt = 0; mt < 2; mt++) {
                    mma_tf32(acc[mt][2*j],   af[mt], b0a, b1a);
                    mma_tf32(acc[mt][2*j+1], af[mt], b0b, b1b);
                }
            }
        }
    }
    __syncthreads();   // all ldsm reads done before Cs overwrites staging

    // ---- epilogue: acc + bias, relu -> Cs ----
    #pragma unroll
    for (int mt = 0; mt < 2; mt++) {
        int row = wr*32 + mt*16 + g;
        #pragma unroll
        for (int nt = 0; nt < 16; nt++) {
            int col = wc*128 + nt*8 + t*2;
            Cs[row*(CC+1) + col]       = fmaxf(acc[mt][nt][0] + bipS[col],   0.f);
            Cs[row*(CC+1) + col + 1]   = fmaxf(acc[mt][nt][1] + bipS[col+1], 0.f);
            Cs[(row+8)*(CC+1) + col]   = fmaxf(acc[mt][nt][2] + bipS[col],   0.f);
            Cs[(row+8)*(CC+1) + col+1] = fmaxf(acc[mt][nt][3] + bipS[col+1], 0.f);
        }
    }
    __syncthreads();

    // ---- LN per row + fused scores (warp per row) ----
    int w = wid;
    for (int r = w; r < TM; r += 8) {
        float vals[8]; float s = 0.f, s2 = 0.f;
        #pragma unroll
        for (int i = 0; i < 8; i++) {
            float x = Cs[r*(CC+1) + lane + 32*i];
            vals[i] = x; s += x; s2 += x*x;
        }
        #pragma unroll
        for (int o = 16; o; o >>= 1) {
            s  += __shfl_xor_sync(0xffffffffu, s,  o);
            s2 += __shfl_xor_sync(0xffffffffu, s2, o);
        }
        float mean = s * (1.f/CC);
        float rstd = rsqrtf(s2*(1.f/CC) - mean*mean + 1e-5f);
        float ph[8];
        #pragma unroll
        for (int h = 0; h < 8; h++) ph[h] = 0.f;
        #pragma unroll
        for (int i = 0; i < 8; i++) {
            int c = lane + 32*i;
            float m = (vals[i] - mean) * rstd * gS[c] + bS[c];
            Cs[r*(CC+1) + c] = m;
            #pragma unroll
            for (int h = 0; h < 8; h++) ph[h] = fmaf(m, wts[h*CC + c], ph[h]);
        }
        #pragma unroll
        for (int h = 0; h < 8; h++)
            #pragma unroll
            for (int o = 16; o; o >>= 1) ph[h] += __shfl_xor_sync(0xffffffffu, ph[h], o);
        if (lane == 0) {
            #pragma unroll
            for (int h = 0; h < 8; h++) {
                float sc = (ph[h] + cbS[h]) * ATT_SCALE
                         * ior[((size_t)(b*NHH + h))*LL + l0 + r];
                Ss[r*NHH + h] = sc;
            }
        }
    }
    __syncthreads();

    // ---- chunk-local softmax: warp h handles head h ----
    {
        float sv[4]; float mx = -1e30f;
        #pragma unroll
        for (int tt = 0; tt < 4; tt++) {
            float sc = Ss[(lane + 32*tt)*NHH + w];
            sv[tt] = sc; mx = fmaxf(mx, sc);
        }
        #pragma unroll
        for (int o = 16; o; o >>= 1) mx = fmaxf(mx, __shfl_xor_sync(0xffffffffu, mx, o));
        float sum = 0.f;
        #pragma unroll
        for (int tt = 0; tt < 4; tt++) {
            float p = __expf(sv[tt] - mx);
            Pm[(lane + 32*tt)*NHH + w] = p;
            sum += p;
        }
        #pragma unroll
        for (int o = 16; o; o >>= 1) sum += __shfl_xor_sync(0xffffffffu, sum, o);
        if (lane == 0) {
            g_pmax[(b*NHH + w)*CHUNKS + chunk] = mx;
            g_psum[(b*NHH + w)*CHUNKS + chunk] = sum;
        }
    }
    __syncthreads();

    // ---- partial weighted-m accumulation ----
    float a8[8];
    #pragma unroll
    for (int h = 0; h < 8; h++) a8[h] = 0.f;
    int c = tid;
    #pragma unroll 2
    for (int r = 0; r < TM; r++) {
        float m = Cs[r*(CC+1) + c];
        float4 p0 = *(float4*)&Pm[r*NHH];
        float4 p1 = *(float4*)&Pm[r*NHH + 4];
        a8[0] = fmaf(p0.x, m, a8[0]);
        a8[1] = fmaf(p0.y, m, a8[1]);
        a8[2] = fmaf(p0.z, m, a8[2]);
        a8[3] = fmaf(p0.w, m, a8[3]);
        a8[4] = fmaf(p1.x, m, a8[4]);
        a8[5] = fmaf(p1.y, m, a8[5]);
        a8[6] = fmaf(p1.z, m, a8[6]);
        a8[7] = fmaf(p1.w, m, a8[7]);
    }
    #pragma unroll
    for (int h = 0; h < 8; h++)
        g_pacc[((size_t)(b*NHH + h)*CHUNKS + chunk)*CC + c] = a8[h];
}

// ============================================================
// Kernel 3: combine chunk partials (unchanged)
// ============================================================
__global__ void reduce_kernel() {
    __shared__ float wfac[CHUNKS];
    __shared__ float red[32];
    __shared__ float s_gmax;
    int bh = blockIdx.x, tid = threadIdx.x;
    int lane = tid & 31, w = tid >> 5;

    float v = (tid < CHUNKS) ? g_pmax[bh*CHUNKS + tid] : -1e30f;
    float m = v;
    #pragma unroll
    for (int o = 16; o; o >>= 1) m = fmaxf(m, __shfl_xor_sync(0xffffffffu, m, o));
    if (lane == 0) red[w] = m;
    __syncthreads();
    if (w == 0) {
        float r = (lane < 8) ? red[lane] : -1e30f;
        #pragma unroll
        for (int o = 4; o; o >>= 1) r = fmaxf(r, __shfl_xor_sync(0xffffffffu, r, o));
        if (lane == 0) s_gmax = r;
    }
    __syncthreads();
    float gmax = s_gmax;

    float contrib = 0.f;
    if (tid < CHUNKS) {
        float wf = __expf(v - gmax);
        wfac[tid] = wf;
        contrib = wf * g_psum[bh*CHUNKS + tid];
    }
    float tot = blk_sum(contrib, red);
    float inv = 1.f / tot;

    int c = tid;
    float acc = 0.f;
    const float* pa = g_pacc + (size_t)bh*CHUNKS*CC;
    #pragma unroll 4
    for (int i = 0; i < CHUNKS; i++) acc = fmaf(pa[(size_t)i*CC + c], wfac[i], acc);
    g_wm[bh*CC + c] = acc * inv;
}

// ============================================================
// Kernel 4: Wv + residual + LN + FFN — 512 threads, split dot-products
// ============================================================
__global__ __launch_bounds__(512, 1)
void final_kernel(const float* __restrict__ query,
                  const float* __restrict__ W_kv, const float* __restrict__ b_kv,
                  const float* __restrict__ g_f,  const float* __restrict__ be_f,
                  const float* __restrict__ W1,   const float* __restrict__ b1,
                  const float* __restrict__ W2,   const float* __restrict__ b2,
                  float* __restrict__ out) {
    __shared__ float wm[NHH*CC], xs[CC], hb[CC], tf[2*CC], red[32], part[512];
    int b = blockIdx.x, tid = threadIdx.x;
    for (int i = tid; i < NHH*CC; i += 512) wm[i] = g_wm[b*NHH*CC + i];
    __syncthreads();

    // Wv projection: split c-range in half across thread pairs
    {
        int j = tid & 255, half = tid >> 8, h = j >> 5;
        const float* wmh = wm + h*CC;
        float o = 0.f;
        int c0 = half * 128;
        #pragma unroll 8
        for (int c = c0; c < c0 + 128; c++)
            o = fmaf(wmh[c], W_kv[c*(2*CC) + CC + j], o);
        part[tid] = o;
    }
    __syncthreads();
    float x = 0.f;
    if (tid < CC) {
        x = part[tid] + part[tid + 256] + b_kv[CC + tid] + query[b*CC + tid];
        xs[tid] = x;
    }
    __syncthreads();

    float s  = blk_sum(x, red);
    float s2 = blk_sum(x*x, red);
    float mean = s * (1.f/CC);
    float rstd = rsqrtf(s2*(1.f/CC) - mean*mean + 1e-5f);
    if (tid < CC) hb[tid] = (x - mean) * rstd * g_f[tid] + be_f[tid];
    __syncthreads();

    // FFN up: one f per thread (512 units)
    {
        int f = tid;
        float a = b1[f];
        #pragma unroll 8
        for (int c = 0; c < CC; c++) a = fmaf(hb[c], W1[c*(2*CC) + f], a);
        tf[f] = 0.5f * a * (1.f + erff(a * 0.7071067811865475f));
    }
    __syncthreads();

    // FFN down: split f-range in half across thread pairs
    {
        int j = tid & 255, half = tid >> 8;
        float y = 0.f;
        int f0 = half * 256;
        #pragma unroll 8
        for (int f = f0; f < f0 + 256; f++)
            y = fmaf(tf[f], W2[f*CC + j], y);
        part[tid] = y;
    }
    __syncthreads();
    if (tid < CC)
        out[b*CC + tid] = xs[tid] + part[tid] + part[tid + 256] + b2[tid];
}

// ============================================================
extern "C" void kernel_launch(void* const* d_in, const int* in_sizes, int n_in,
                              void* d_out, int out_size) {
    const float* query = (const float*)d_in[0];
    const float* mem   = (const float*)d_in[1];
    const float* ior   = (const float*)d_in[2];
    const float* W_ip  = (const float*)d_in[3];
    const float* b_ip  = (const float*)d_in[4];
    const float* g_ip  = (const float*)d_in[5];
    const float* be_ip = (const float*)d_in[6];
    const float* W_q   = (const float*)d_in[7];
    const float* b_q   = (const float*)d_in[8];
    const float* W_kv  = (const float*)d_in[9];
    const float* b_kv  = (const float*)d_in[10];
    const float* g_q   = (const float*)d_in[11];
    const float* be_q  = (const float*)d_in[12];
    const float* g_f   = (const float*)d_in[13];
    const float* be_f  = (const float*)d_in[14];
    const float* W1    = (const float*)d_in[15];
    const float* b1    = (const float*)d_in[16];
    const float* W2    = (const float*)d_in[17];
    const float* b2    = (const float*)d_in[18];
    float* out = (float*)d_out;

    transpose_wip<<<dim3(8, 8), dim3(32, 32)>>>(W_ip);
    prep_kernel<<<BB, NT>>>(query, W_q, b_q, W_kv, b_kv, g_q, be_q);

    cudaFuncSetAttribute(main_kernel, cudaFuncAttributeMaxDynamicSharedMemorySize,
                         SMEM_BYTES);
    main_kernel<<<dim3(CHUNKS, BB), NT, SMEM_BYTES>>>(mem, b_ip, g_ip, be_ip, ior);

    reduce_kernel<<<BB*NHH, NT>>>();
    final_kernel<<<BB, 512>>>(query, W_kv, b_kv, g_f, be_f, W1, b1, W2, b2, out);
}